// round 3
// baseline (speedup 1.0000x reference)
#include <cuda_runtime.h>
#include <cstdint>
#include <cstddef>

#define BB      8
#define SS      1024
#define DMODEL  512
#define NHEAD   8
#define HDIM    64
#define SCPAD   1032
#define SCALE_F 0.044194173824159216f   // 1/sqrt(512)

// ---------------- static scratch (no runtime allocation) ----------------
__device__ float g_qh[BB * NHEAD * SS * HDIM];   // [b][n][s][d]
__device__ float g_kh[BB * NHEAD * SS * HDIM];
__device__ float g_vh[BB * NHEAD * SS * HDIM];
__device__ float g_ph[BB * NHEAD * SS * HDIM];
__device__ float g_ctx[BB * SS * DMODEL];        // [b][s][n*64+d]

// ---------------- batched projection GEMM ----------------
// C[i][j] = sum_k X[i][k] * W[j][k] (+ bias[j])
// M = 8192 rows, N = 512 cols, K = 512. Tile 128x128x16, 256 thr, 8x8 micro.
struct ProjArgs {
    const float* X[4];
    const float* W[4];
    const float* bias[4];   // nullptr -> no bias
    float*       out[4];
    int          head_mode; // 1: write [b][n][s][d] layout, 0: row-major
    int          count;
};

__global__ __launch_bounds__(256, 2)
void gemm_kernel(ProjArgs args)
{
    const int z = blockIdx.z;
    if (z >= args.count) return;
    const float* __restrict__ X    = args.X[z];
    const float* __restrict__ W    = args.W[z];
    const float* __restrict__ bias = args.bias[z];
    float* __restrict__ out        = args.out[z];

    __shared__ float As[16][132];
    __shared__ float Bs[16][132];

    const int t  = threadIdx.x;
    const int ty = t >> 4;          // 0..15
    const int tx = t & 15;          // 0..15
    const int i0 = blockIdx.y * 128;
    const int j0 = blockIdx.x * 128;
    const int lr = t >> 2;          // 0..63
    const int lc = (t & 3) * 4;     // 0,4,8,12

    float acc[8][8];
#pragma unroll
    for (int a = 0; a < 8; a++)
#pragma unroll
        for (int b2 = 0; b2 < 8; b2++) acc[a][b2] = 0.f;

    for (int kk = 0; kk < DMODEL; kk += 16) {
        float4 a0 = *(const float4*)(X + (size_t)(i0 + lr)      * DMODEL + kk + lc);
        float4 a1 = *(const float4*)(X + (size_t)(i0 + lr + 64) * DMODEL + kk + lc);
        float4 b0 = *(const float4*)(W + (size_t)(j0 + lr)      * DMODEL + kk + lc);
        float4 b1 = *(const float4*)(W + (size_t)(j0 + lr + 64) * DMODEL + kk + lc);
        As[lc+0][lr]    = a0.x; As[lc+1][lr]    = a0.y; As[lc+2][lr]    = a0.z; As[lc+3][lr]    = a0.w;
        As[lc+0][lr+64] = a1.x; As[lc+1][lr+64] = a1.y; As[lc+2][lr+64] = a1.z; As[lc+3][lr+64] = a1.w;
        Bs[lc+0][lr]    = b0.x; Bs[lc+1][lr]    = b0.y; Bs[lc+2][lr]    = b0.z; Bs[lc+3][lr]    = b0.w;
        Bs[lc+0][lr+64] = b1.x; Bs[lc+1][lr+64] = b1.y; Bs[lc+2][lr+64] = b1.z; Bs[lc+3][lr+64] = b1.w;
        __syncthreads();
#pragma unroll
        for (int k = 0; k < 16; k++) {
            float ar[8], br[8];
#pragma unroll
            for (int m = 0; m < 8; m++) ar[m] = As[k][ty*8 + m];
#pragma unroll
            for (int m = 0; m < 8; m++) br[m] = Bs[k][tx*8 + m];
#pragma unroll
            for (int a = 0; a < 8; a++)
#pragma unroll
                for (int b2 = 0; b2 < 8; b2++)
                    acc[a][b2] = fmaf(ar[a], br[b2], acc[a][b2]);
        }
        __syncthreads();
    }

    float bfrag[8];
#pragma unroll
    for (int m = 0; m < 8; m++) bfrag[m] = bias ? bias[j0 + tx*8 + m] : 0.f;

    if (args.head_mode) {
#pragma unroll
        for (int a = 0; a < 8; a++) {
            int i  = i0 + ty*8 + a;
            int bb = i >> 10;
            int s  = i & (SS - 1);
#pragma unroll
            for (int jj = 0; jj < 8; jj += 4) {
                int j = j0 + tx*8 + jj;
                int n = j >> 6;
                int d = j & (HDIM - 1);
                float4 vv;
                vv.x = acc[a][jj+0] + bfrag[jj+0];
                vv.y = acc[a][jj+1] + bfrag[jj+1];
                vv.z = acc[a][jj+2] + bfrag[jj+2];
                vv.w = acc[a][jj+3] + bfrag[jj+3];
                *(float4*)(out + (((size_t)bb*NHEAD + n)*SS + s)*HDIM + d) = vv;
            }
        }
    } else {
#pragma unroll
        for (int a = 0; a < 8; a++) {
            int i = i0 + ty*8 + a;
            float* row = out + (size_t)i * DMODEL + j0 + tx*8;
#pragma unroll
            for (int jj = 0; jj < 8; jj += 4) {
                float4 vv;
                vv.x = acc[a][jj+0] + bfrag[jj+0];
                vv.y = acc[a][jj+1] + bfrag[jj+1];
                vv.z = acc[a][jj+2] + bfrag[jj+2];
                vv.w = acc[a][jj+3] + bfrag[jj+3];
                *(float4*)(row + jj) = vv;
            }
        }
    }
}

// ---------------- fused attention ----------------
// One CTA = (b, head, 32 q-rows). Scores [32][1024] resident in smem.
// Rel-shift: P[q][j] scatter-adds to (q, j+q-(S-1)) if j>=S-1-q
//                               and (q-1, j+q+1)   if j+q+1 < S.
__global__ __launch_bounds__(256, 1)
void attn_kernel(const int* __restrict__ mask,
                 const float* __restrict__ u_bias,
                 const float* __restrict__ v_bias,
                 float* __restrict__ attn_out)
{
    extern __shared__ float sm[];
    float* sc   = sm;                     // 32 * 1032
    float* qu   = sc + 32 * SCPAD;        // 32 * 64
    float* qv   = qu + 32 * HDIM;         // 33 * 64
    float* tile = qv + 33 * HDIM;         // 64 * 64
    float* red  = tile + 64 * 64;         // 32 * 8

    const int t  = threadIdx.x;
    const int q0 = blockIdx.x * 32;
    const int n  = blockIdx.y;
    const int b  = blockIdx.z;

    const float* qh_bn = g_qh + ((size_t)(b*NHEAD + n)*SS + q0) * HDIM;
    const float* kh_bn = g_kh + (size_t)(b*NHEAD + n)*SS * HDIM;
    const float* ph_bn = g_ph + (size_t)(b*NHEAD + n)*SS * HDIM;
    const float* vh_bn = g_vh + (size_t)(b*NHEAD + n)*SS * HDIM;

    // load q rows (+u) and (+v_bias); qv needs 33 rows (row q0+32 for shift)
    for (int idx = t; idx < 32*HDIM; idx += 256) {
        int d = idx & (HDIM - 1);
        qu[idx] = qh_bn[idx] + u_bias[n*HDIM + d];
    }
    for (int idx = t; idx < 33*HDIM; idx += 256) {
        int d  = idx & (HDIM - 1);
        int ii = idx >> 6;
        float qval = (q0 + ii < SS) ? qh_bn[idx] : 0.f;
        qv[idx] = qval + v_bias[n*HDIM + d];
    }
    __syncthreads();

    const int li  = t >> 3;          // 0..31 score row
    const int lg  = t & 7;           // 0..7  col group
    const int lj  = t & 63;          // tile load column
    const int ldb = (t >> 6) * 16;   // tile load d-block

    // ---- phase 1: content scores ----
    for (int k0 = 0; k0 < SS; k0 += 64) {
        {   // load khT[d][j]
            const float* src = kh_bn + (size_t)(k0 + lj) * HDIM + ldb;
#pragma unroll
            for (int c = 0; c < 4; c++) {
                float4 v4 = *(const float4*)(src + c*4);
                int d = ldb + c*4;
                tile[(d+0)*64 + lj] = v4.x;
                tile[(d+1)*64 + lj] = v4.y;
                tile[(d+2)*64 + lj] = v4.z;
                tile[(d+3)*64 + lj] = v4.w;
            }
        }
        __syncthreads();
        float cacc[8] = {0.f,0.f,0.f,0.f,0.f,0.f,0.f,0.f};
#pragma unroll 16
        for (int d = 0; d < HDIM; d++) {
            float a = qu[li*HDIM + d];
            const float* tr = tile + d*64 + lg*8;
            float4 t0 = *(const float4*)tr;
            float4 t1 = *(const float4*)(tr + 4);
            cacc[0] = fmaf(a, t0.x, cacc[0]); cacc[1] = fmaf(a, t0.y, cacc[1]);
            cacc[2] = fmaf(a, t0.z, cacc[2]); cacc[3] = fmaf(a, t0.w, cacc[3]);
            cacc[4] = fmaf(a, t1.x, cacc[4]); cacc[5] = fmaf(a, t1.y, cacc[5]);
            cacc[6] = fmaf(a, t1.z, cacc[6]); cacc[7] = fmaf(a, t1.w, cacc[7]);
        }
        float* dst = sc + li*SCPAD + k0 + lg*8;
        *(float4*)dst       = make_float4(cacc[0], cacc[1], cacc[2], cacc[3]);
        *(float4*)(dst + 4) = make_float4(cacc[4], cacc[5], cacc[6], cacc[7]);
        __syncthreads();
    }

    // ---- phase 2: positional scores with relative shift (scatter-add) ----
    for (int j0 = 0; j0 < SS; j0 += 64) {
        {   // load phT[d][j]
            const float* src = ph_bn + (size_t)(j0 + lj) * HDIM + ldb;
#pragma unroll
            for (int c = 0; c < 4; c++) {
                float4 v4 = *(const float4*)(src + c*4);
                int d = ldb + c*4;
                tile[(d+0)*64 + lj] = v4.x;
                tile[(d+1)*64 + lj] = v4.y;
                tile[(d+2)*64 + lj] = v4.z;
                tile[(d+3)*64 + lj] = v4.w;
            }
        }
        __syncthreads();
        float pacc[8] = {0.f,0.f,0.f,0.f,0.f,0.f,0.f,0.f};
#pragma unroll 16
        for (int d = 0; d < HDIM; d++) {
            float a = qv[li*HDIM + d];
            const float* tr = tile + d*64 + lg*8;
            float4 t0 = *(const float4*)tr;
            float4 t1 = *(const float4*)(tr + 4);
            pacc[0] = fmaf(a, t0.x, pacc[0]); pacc[1] = fmaf(a, t0.y, pacc[1]);
            pacc[2] = fmaf(a, t0.z, pacc[2]); pacc[3] = fmaf(a, t0.w, pacc[3]);
            pacc[4] = fmaf(a, t1.x, pacc[4]); pacc[5] = fmaf(a, t1.y, pacc[5]);
            pacc[6] = fmaf(a, t1.z, pacc[6]); pacc[7] = fmaf(a, t1.w, pacc[7]);
        }
        const int qq = q0 + li;
#pragma unroll
        for (int m = 0; m < 8; m++) {
            int jj = j0 + lg*8 + m;
            int k1 = jj + qq - (SS - 1);
            if (k1 >= 0) sc[li*SCPAD + k1] += pacc[m];
            int k2 = jj + qq + 1;
            if (li >= 1 && k2 < SS) sc[(li-1)*SCPAD + k2] += pacc[m];
        }
        // extra source row q0+32 (feeds row 31's k>q+1 region)
        if (t < 64) {
            float p32 = 0.f;
            const float* qv32 = qv + 32*HDIM;
#pragma unroll 16
            for (int d = 0; d < HDIM; d++)
                p32 = fmaf(qv32[d], tile[d*64 + t], p32);
            int k2 = (j0 + t) + (q0 + 32) + 1;
            if (k2 < SS) sc[31*SCPAD + k2] += p32;
        }
        __syncthreads();
    }

    // ---- phase 3: mask (int32 nonzero = masked), scale, softmax, write attn ----
    const int* mrow = mask + ((size_t)b*SS + (q0 + li)) * SS;
    float* srow = sc + li*SCPAD;
    float mx = -3.402823e38f;
#pragma unroll
    for (int c = 0; c < 16; c++) {
        int k = lg*8 + c*64;
        float4 s0 = *(float4*)(srow + k);
        float4 s1 = *(float4*)(srow + k + 4);
        int4 m0 = *(const int4*)(mrow + k);
        int4 m1 = *(const int4*)(mrow + k + 4);
        s0.x = m0.x ? -10000.f : s0.x * SCALE_F;
        s0.y = m0.y ? -10000.f : s0.y * SCALE_F;
        s0.z = m0.z ? -10000.f : s0.z * SCALE_F;
        s0.w = m0.w ? -10000.f : s0.w * SCALE_F;
        s1.x = m1.x ? -10000.f : s1.x * SCALE_F;
        s1.y = m1.y ? -10000.f : s1.y * SCALE_F;
        s1.z = m1.z ? -10000.f : s1.z * SCALE_F;
        s1.w = m1.w ? -10000.f : s1.w * SCALE_F;
        *(float4*)(srow + k)     = s0;
        *(float4*)(srow + k + 4) = s1;
        mx = fmaxf(mx, fmaxf(fmaxf(fmaxf(s0.x, s0.y), fmaxf(s0.z, s0.w)),
                             fmaxf(fmaxf(s1.x, s1.y), fmaxf(s1.z, s1.w))));
    }
    red[li*8 + lg] = mx;
    __syncthreads();
    float rmax = red[li*8 + 0];
#pragma unroll
    for (int m = 1; m < 8; m++) rmax = fmaxf(rmax, red[li*8 + m]);
    __syncthreads();

    float sum = 0.f;
#pragma unroll
    for (int c = 0; c < 16; c++) {
        int k = lg*8 + c*64;
        float4 s0 = *(float4*)(srow + k);
        float4 s1 = *(float4*)(srow + k + 4);
        s0.x = __expf(s0.x - rmax); s0.y = __expf(s0.y - rmax);
        s0.z = __expf(s0.z - rmax); s0.w = __expf(s0.w - rmax);
        s1.x = __expf(s1.x - rmax); s1.y = __expf(s1.y - rmax);
        s1.z = __expf(s1.z - rmax); s1.w = __expf(s1.w - rmax);
        sum += (s0.x + s0.y + s0.z + s0.w) + (s1.x + s1.y + s1.z + s1.w);
        *(float4*)(srow + k)     = s0;
        *(float4*)(srow + k + 4) = s1;
    }
    red[li*8 + lg] = sum;
    __syncthreads();
    float tsum = 0.f;
#pragma unroll
    for (int m = 0; m < 8; m++) tsum += red[li*8 + m];
    const float inv = 1.f / tsum;

    float* arow = attn_out + (((size_t)(b*NHEAD + n)*SS) + q0 + li) * SS;
#pragma unroll
    for (int c = 0; c < 16; c++) {
        int k = lg*8 + c*64;
        float4 s0 = *(float4*)(srow + k);
        float4 s1 = *(float4*)(srow + k + 4);
        s0.x *= inv; s0.y *= inv; s0.z *= inv; s0.w *= inv;
        s1.x *= inv; s1.y *= inv; s1.z *= inv; s1.w *= inv;
        *(float4*)(arow + k)     = s0;
        *(float4*)(arow + k + 4) = s1;
    }

    // ---- phase 4: context = attn @ V (unnormalized p in smem, scale by inv) ----
    float oacc[8] = {0.f,0.f,0.f,0.f,0.f,0.f,0.f,0.f};
    for (int k0 = 0; k0 < SS; k0 += 64) {
        __syncthreads();
        // linear copy of v tile [kk][d]
#pragma unroll
        for (int c = 0; c < 4; c++) {
            int f = (t + 256*c) * 4;
            *(float4*)(tile + f) = *(const float4*)(vh_bn + (size_t)k0*HDIM + f);
        }
        __syncthreads();
#pragma unroll 16
        for (int kk = 0; kk < 64; kk++) {
            float p = srow[k0 + kk];
            const float* tr = tile + kk*64 + lg*8;
            float4 t0 = *(const float4*)tr;
            float4 t1 = *(const float4*)(tr + 4);
            oacc[0] = fmaf(p, t0.x, oacc[0]); oacc[1] = fmaf(p, t0.y, oacc[1]);
            oacc[2] = fmaf(p, t0.z, oacc[2]); oacc[3] = fmaf(p, t0.w, oacc[3]);
            oacc[4] = fmaf(p, t1.x, oacc[4]); oacc[5] = fmaf(p, t1.y, oacc[5]);
            oacc[6] = fmaf(p, t1.z, oacc[6]); oacc[7] = fmaf(p, t1.w, oacc[7]);
        }
    }
    float* crow = g_ctx + ((size_t)b*SS + q0 + li) * DMODEL + n*HDIM + lg*8;
    float4 o0 = make_float4(oacc[0]*inv, oacc[1]*inv, oacc[2]*inv, oacc[3]*inv);
    float4 o1 = make_float4(oacc[4]*inv, oacc[5]*inv, oacc[6]*inv, oacc[7]*inv);
    *(float4*)crow       = o0;
    *(float4*)(crow + 4) = o1;
}

// ---------------- launcher ----------------
extern "C" void kernel_launch(void* const* d_in, const int* in_sizes, int n_in,
                              void* d_out, int out_size)
{
    (void)in_sizes; (void)n_in; (void)out_size;
    const float* q    = (const float*)d_in[0];
    const float* k    = (const float*)d_in[1];
    const float* v    = (const float*)d_in[2];
    const float* pos  = (const float*)d_in[3];
    const int*   mask = (const int*)d_in[4];
    const float* Wq   = (const float*)d_in[5];
    const float* bq   = (const float*)d_in[6];
    const float* Wk   = (const float*)d_in[7];
    const float* bk   = (const float*)d_in[8];
    const float* Wv   = (const float*)d_in[9];
    const float* bv   = (const float*)d_in[10];
    const float* Wpos = (const float*)d_in[11];
    const float* Wout = (const float*)d_in[12];
    const float* bout = (const float*)d_in[13];
    const float* u    = (const float*)d_in[14];
    const float* vb   = (const float*)d_in[15];

    float *p_qh, *p_kh, *p_vh, *p_ph, *p_ctx;
    cudaGetSymbolAddress((void**)&p_qh,  g_qh);
    cudaGetSymbolAddress((void**)&p_kh,  g_kh);
    cudaGetSymbolAddress((void**)&p_vh,  g_vh);
    cudaGetSymbolAddress((void**)&p_ph,  g_ph);
    cudaGetSymbolAddress((void**)&p_ctx, g_ctx);

    const int smem = (32*SCPAD + 32*HDIM + 33*HDIM + 64*64 + 32*8) * (int)sizeof(float);
    cudaFuncSetAttribute(attn_kernel, cudaFuncAttributeMaxDynamicSharedMemorySize, smem);

    // 4 input projections in one launch (grid.z picks the projection)
    ProjArgs pa;
    pa.X[0] = q;   pa.W[0] = Wq;   pa.bias[0] = bq;      pa.out[0] = p_qh;
    pa.X[1] = k;   pa.W[1] = Wk;   pa.bias[1] = bk;      pa.out[1] = p_kh;
    pa.X[2] = v;   pa.W[2] = Wv;   pa.bias[2] = bv;      pa.out[2] = p_vh;
    pa.X[3] = pos; pa.W[3] = Wpos; pa.bias[3] = nullptr; pa.out[3] = p_ph;
    pa.head_mode = 1;
    pa.count = 4;
    dim3 gproj(DMODEL/128, (BB*SS)/128, 4);
    gemm_kernel<<<gproj, 256>>>(pa);

    float* attn_out = (float*)d_out + (size_t)BB*SS*DMODEL;
    attn_kernel<<<dim3(SS/32, NHEAD, BB), 256, smem>>>(mask, u, vb, attn_out);

    // output projection: context @ Wout.T + bout -> d_out[0 : B*S*DIM]
    ProjArgs po;
    po.X[0] = p_ctx; po.W[0] = Wout; po.bias[0] = bout; po.out[0] = (float*)d_out;
    po.head_mode = 0;
    po.count = 1;
    dim3 gout(DMODEL/128, (BB*SS)/128, 1);
    gemm_kernel<<<gout, 256>>>(po);
}

// round 14
// speedup vs baseline: 1.2955x; 1.2955x over previous
#include <cuda_runtime.h>
#include <cstdint>
#include <cstddef>

#define BB      8
#define SS      1024
#define DMODEL  512
#define NHEAD   8
#define HDIM    64
#define SCPAD   1032
#define TSTR    68      // tile row stride (floats), pad vs 64
#define QSTR    68      // qu/qv row stride
#define SCALE_F 0.044194173824159216f   // 1/sqrt(512)

// ---------------- static scratch (no runtime allocation) ----------------
__device__ float g_qh[BB * NHEAD * SS * HDIM];   // [b][n][s][d]
__device__ float g_kh[BB * NHEAD * SS * HDIM];
__device__ float g_vh[BB * NHEAD * SS * HDIM];
__device__ float g_ph[BB * NHEAD * SS * HDIM];
__device__ float g_ctx[BB * SS * DMODEL];        // [b][s][n*64+d]

// ---------------- batched projection GEMM ----------------
struct ProjArgs {
    const float* X[4];
    const float* W[4];
    const float* bias[4];   // nullptr -> no bias
    float*       out[4];
    int          head_mode;
    int          count;
};

__global__ __launch_bounds__(256, 2)
void gemm_kernel(ProjArgs args)
{
    const int z = blockIdx.z;
    if (z >= args.count) return;
    const float* __restrict__ X    = args.X[z];
    const float* __restrict__ W    = args.W[z];
    const float* __restrict__ bias = args.bias[z];
    float* __restrict__ out        = args.out[z];

    __shared__ float As[16][132];
    __shared__ float Bs[16][132];

    const int t  = threadIdx.x;
    const int ty = t >> 4;
    const int tx = t & 15;
    const int i0 = blockIdx.y * 128;
    const int j0 = blockIdx.x * 128;
    const int lr = t >> 2;
    const int lc = (t & 3) * 4;

    float acc[8][8];
#pragma unroll
    for (int a = 0; a < 8; a++)
#pragma unroll
        for (int b2 = 0; b2 < 8; b2++) acc[a][b2] = 0.f;

    for (int kk = 0; kk < DMODEL; kk += 16) {
        float4 a0 = *(const float4*)(X + (size_t)(i0 + lr)      * DMODEL + kk + lc);
        float4 a1 = *(const float4*)(X + (size_t)(i0 + lr + 64) * DMODEL + kk + lc);
        float4 b0 = *(const float4*)(W + (size_t)(j0 + lr)      * DMODEL + kk + lc);
        float4 b1 = *(const float4*)(W + (size_t)(j0 + lr + 64) * DMODEL + kk + lc);
        As[lc+0][lr]    = a0.x; As[lc+1][lr]    = a0.y; As[lc+2][lr]    = a0.z; As[lc+3][lr]    = a0.w;
        As[lc+0][lr+64] = a1.x; As[lc+1][lr+64] = a1.y; As[lc+2][lr+64] = a1.z; As[lc+3][lr+64] = a1.w;
        Bs[lc+0][lr]    = b0.x; Bs[lc+1][lr]    = b0.y; Bs[lc+2][lr]    = b0.z; Bs[lc+3][lr]    = b0.w;
        Bs[lc+0][lr+64] = b1.x; Bs[lc+1][lr+64] = b1.y; Bs[lc+2][lr+64] = b1.z; Bs[lc+3][lr+64] = b1.w;
        __syncthreads();
#pragma unroll
        for (int k = 0; k < 16; k++) {
            float ar[8], br[8];
#pragma unroll
            for (int m = 0; m < 8; m++) ar[m] = As[k][ty*8 + m];
#pragma unroll
            for (int m = 0; m < 8; m++) br[m] = Bs[k][tx*8 + m];
#pragma unroll
            for (int a = 0; a < 8; a++)
#pragma unroll
                for (int b2 = 0; b2 < 8; b2++)
                    acc[a][b2] = fmaf(ar[a], br[b2], acc[a][b2]);
        }
        __syncthreads();
    }

    float bfrag[8];
#pragma unroll
    for (int m = 0; m < 8; m++) bfrag[m] = bias ? bias[j0 + tx*8 + m] : 0.f;

    if (args.head_mode) {
#pragma unroll
        for (int a = 0; a < 8; a++) {
            int i  = i0 + ty*8 + a;
            int bb = i >> 10;
            int s  = i & (SS - 1);
#pragma unroll
            for (int jj = 0; jj < 8; jj += 4) {
                int j = j0 + tx*8 + jj;
                int n = j >> 6;
                int d = j & (HDIM - 1);
                float4 vv;
                vv.x = acc[a][jj+0] + bfrag[jj+0];
                vv.y = acc[a][jj+1] + bfrag[jj+1];
                vv.z = acc[a][jj+2] + bfrag[jj+2];
                vv.w = acc[a][jj+3] + bfrag[jj+3];
                *(float4*)(out + (((size_t)bb*NHEAD + n)*SS + s)*HDIM + d) = vv;
            }
        }
    } else {
#pragma unroll
        for (int a = 0; a < 8; a++) {
            int i = i0 + ty*8 + a;
            float* row = out + (size_t)i * DMODEL + j0 + tx*8;
#pragma unroll
            for (int jj = 0; jj < 8; jj += 4) {
                float4 vv;
                vv.x = acc[a][jj+0] + bfrag[jj+0];
                vv.y = acc[a][jj+1] + bfrag[jj+1];
                vv.z = acc[a][jj+2] + bfrag[jj+2];
                vv.w = acc[a][jj+3] + bfrag[jj+3];
                *(float4*)(row + jj) = vv;
            }
        }
    }
}

// ---------------- fused attention, register-tiled ----------------
// CTA = (b, head, 32 q-rows). Threads: cg=t&7 (8 cols), rg=(t>>3)&7 (4 rows),
// kt=t>>6 (64-col subtile / k-quarter). k processed in 256-col blocks.
__global__ __launch_bounds__(256, 1)
void attn_kernel(const int* __restrict__ mask,
                 const float* __restrict__ u_bias,
                 const float* __restrict__ v_bias,
                 float* __restrict__ attn_out)
{
    extern __shared__ float sm[];
    float* sc   = sm;                       // 32 * 1032
    float* tile = sc + 32 * SCPAD;          // 256 * 68
    float* qu   = tile + 256 * TSTR;        // 32 * 68
    float* qv   = qu + 32 * QSTR;           // 33 * 68
    float* red  = qv + 33 * QSTR;           // 256

    const int t  = threadIdx.x;
    const int q0 = blockIdx.x * 32;
    const int n  = blockIdx.y;
    const int b  = blockIdx.z;

    const float* qh_bn = g_qh + ((size_t)(b*NHEAD + n)*SS + q0) * HDIM;
    const float* kh_bn = g_kh + (size_t)(b*NHEAD + n)*SS * HDIM;
    const float* ph_bn = g_ph + (size_t)(b*NHEAD + n)*SS * HDIM;
    const float* vh_bn = g_vh + (size_t)(b*NHEAD + n)*SS * HDIM;

    // load q rows (+u) and (+v_bias) with padded stride
    for (int idx = t; idx < 32*HDIM; idx += 256) {
        int r = idx >> 6, d = idx & 63;
        qu[r*QSTR + d] = qh_bn[r*HDIM + d] + u_bias[n*HDIM + d];
    }
    for (int idx = t; idx < 33*HDIM; idx += 256) {
        int r = idx >> 6, d = idx & 63;
        float qval = (q0 + r < SS) ? qh_bn[r*HDIM + d] : 0.f;
        qv[r*QSTR + d] = qval + v_bias[n*HDIM + d];
    }
    __syncthreads();

    const int cg   = t & 7;
    const int rg   = (t >> 3) & 7;
    const int kt   = t >> 6;
    const int r0   = rg * 4;
    const int c0   = kt * 64 + cg * 8;
    const int lrow = t >> 2;            // loader: row within pass
    const int ldo  = (t & 3) * 16;      // loader: d offset

    // ---- phase 1: content scores ----
    for (int kb = 0; kb < SS; kb += 256) {
#pragma unroll
        for (int p = 0; p < 4; p++) {
            int row = p*64 + lrow;
            const float* src = kh_bn + (size_t)(kb + row)*HDIM + ldo;
            float* dst = tile + row*TSTR + ldo;
#pragma unroll
            for (int c = 0; c < 4; c++)
                *(float4*)(dst + c*4) = *(const float4*)(src + c*4);
        }
        __syncthreads();
        float acc[4][8];
#pragma unroll
        for (int rr = 0; rr < 4; rr++)
#pragma unroll
            for (int cc = 0; cc < 8; cc++) acc[rr][cc] = 0.f;
#pragma unroll 2
        for (int d4 = 0; d4 < HDIM; d4 += 4) {
            float4 a0 = *(const float4*)(qu + (r0+0)*QSTR + d4);
            float4 a1 = *(const float4*)(qu + (r0+1)*QSTR + d4);
            float4 a2 = *(const float4*)(qu + (r0+2)*QSTR + d4);
            float4 a3 = *(const float4*)(qu + (r0+3)*QSTR + d4);
#pragma unroll
            for (int cc = 0; cc < 8; cc++) {
                float4 bb = *(const float4*)(tile + (c0+cc)*TSTR + d4);
                acc[0][cc] = fmaf(a0.x, bb.x, fmaf(a0.y, bb.y, fmaf(a0.z, bb.z, fmaf(a0.w, bb.w, acc[0][cc]))));
                acc[1][cc] = fmaf(a1.x, bb.x, fmaf(a1.y, bb.y, fmaf(a1.z, bb.z, fmaf(a1.w, bb.w, acc[1][cc]))));
                acc[2][cc] = fmaf(a2.x, bb.x, fmaf(a2.y, bb.y, fmaf(a2.z, bb.z, fmaf(a2.w, bb.w, acc[2][cc]))));
                acc[3][cc] = fmaf(a3.x, bb.x, fmaf(a3.y, bb.y, fmaf(a3.z, bb.z, fmaf(a3.w, bb.w, acc[3][cc]))));
            }
        }
#pragma unroll
        for (int rr = 0; rr < 4; rr++) {
            float* dst = sc + (r0+rr)*SCPAD + kb + c0;
            *(float4*)dst       = make_float4(acc[rr][0], acc[rr][1], acc[rr][2], acc[rr][3]);
            *(float4*)(dst + 4) = make_float4(acc[rr][4], acc[rr][5], acc[rr][6], acc[rr][7]);
        }
        __syncthreads();
    }

    // ---- phase 2: positional scores, scatter rel-shift ----
    for (int kb = 0; kb < SS; kb += 256) {
#pragma unroll
        for (int p = 0; p < 4; p++) {
            int row = p*64 + lrow;
            const float* src = ph_bn + (size_t)(kb + row)*HDIM + ldo;
            float* dst = tile + row*TSTR + ldo;
#pragma unroll
            for (int c = 0; c < 4; c++)
                *(float4*)(dst + c*4) = *(const float4*)(src + c*4);
        }
        __syncthreads();
        float acc[4][8];
#pragma unroll
        for (int rr = 0; rr < 4; rr++)
#pragma unroll
            for (int cc = 0; cc < 8; cc++) acc[rr][cc] = 0.f;
#pragma unroll 2
        for (int d4 = 0; d4 < HDIM; d4 += 4) {
            float4 a0 = *(const float4*)(qv + (r0+0)*QSTR + d4);
            float4 a1 = *(const float4*)(qv + (r0+1)*QSTR + d4);
            float4 a2 = *(const float4*)(qv + (r0+2)*QSTR + d4);
            float4 a3 = *(const float4*)(qv + (r0+3)*QSTR + d4);
#pragma unroll
            for (int cc = 0; cc < 8; cc++) {
                float4 bb = *(const float4*)(tile + (c0+cc)*TSTR + d4);
                acc[0][cc] = fmaf(a0.x, bb.x, fmaf(a0.y, bb.y, fmaf(a0.z, bb.z, fmaf(a0.w, bb.w, acc[0][cc]))));
                acc[1][cc] = fmaf(a1.x, bb.x, fmaf(a1.y, bb.y, fmaf(a1.z, bb.z, fmaf(a1.w, bb.w, acc[1][cc]))));
                acc[2][cc] = fmaf(a2.x, bb.x, fmaf(a2.y, bb.y, fmaf(a2.z, bb.z, fmaf(a2.w, bb.w, acc[2][cc]))));
                acc[3][cc] = fmaf(a3.x, bb.x, fmaf(a3.y, bb.y, fmaf(a3.z, bb.z, fmaf(a3.w, bb.w, acc[3][cc]))));
            }
        }
        // scatter: P[q][j] -> sc[q][j+q-1023] (j>=1023-q); -> sc[q-1][j+q+1] (if valid)
#pragma unroll
        for (int rr = 0; rr < 4; rr++) {
            int lrw = r0 + rr;
            int qq  = q0 + lrw;
#pragma unroll
            for (int cc = 0; cc < 8; cc++) {
                int j  = kb + c0 + cc;
                int k1 = j + qq - (SS - 1);
                if (k1 >= 0) sc[lrw*SCPAD + k1] += acc[rr][cc];
                int k2 = j + qq + 1;
                if (lrw >= 1 && k2 < SS) sc[(lrw-1)*SCPAD + k2] += acc[rr][cc];
            }
        }
        // feeder row q0+32 -> sc row 31 (k > q+1 region)
        {
            float p32 = 0.f;
            const float* qv32 = qv + 32*QSTR;
            const float* tcol = tile + t*TSTR;
#pragma unroll
            for (int d4 = 0; d4 < HDIM; d4 += 4) {
                float4 qa = *(const float4*)(qv32 + d4);
                float4 tb = *(const float4*)(tcol + d4);
                p32 = fmaf(qa.x, tb.x, fmaf(qa.y, tb.y, fmaf(qa.z, tb.z, fmaf(qa.w, tb.w, p32))));
            }
            int k2 = kb + t + q0 + 33;
            if (k2 < SS) sc[31*SCPAD + k2] += p32;
        }
        __syncthreads();
    }

    // ---- phase 3: mask (int32 nonzero = masked), scale, softmax, write attn ----
    const int li = t >> 3;
    const int lg = t & 7;
    const int* mrow = mask + ((size_t)b*SS + (q0 + li)) * SS;
    float* srow = sc + li*SCPAD;
    float mx = -3.402823e38f;
#pragma unroll
    for (int c = 0; c < 16; c++) {
        int k = lg*8 + c*64;
        float4 s0 = *(float4*)(srow + k);
        float4 s1 = *(float4*)(srow + k + 4);
        int4 m0 = *(const int4*)(mrow + k);
        int4 m1 = *(const int4*)(mrow + k + 4);
        s0.x = m0.x ? -10000.f : s0.x * SCALE_F;
        s0.y = m0.y ? -10000.f : s0.y * SCALE_F;
        s0.z = m0.z ? -10000.f : s0.z * SCALE_F;
        s0.w = m0.w ? -10000.f : s0.w * SCALE_F;
        s1.x = m1.x ? -10000.f : s1.x * SCALE_F;
        s1.y = m1.y ? -10000.f : s1.y * SCALE_F;
        s1.z = m1.z ? -10000.f : s1.z * SCALE_F;
        s1.w = m1.w ? -10000.f : s1.w * SCALE_F;
        *(float4*)(srow + k)     = s0;
        *(float4*)(srow + k + 4) = s1;
        mx = fmaxf(mx, fmaxf(fmaxf(fmaxf(s0.x, s0.y), fmaxf(s0.z, s0.w)),
                             fmaxf(fmaxf(s1.x, s1.y), fmaxf(s1.z, s1.w))));
    }
    red[li*8 + lg] = mx;
    __syncthreads();
    float rmax = red[li*8 + 0];
#pragma unroll
    for (int m = 1; m < 8; m++) rmax = fmaxf(rmax, red[li*8 + m]);
    __syncthreads();

    float sum = 0.f;
#pragma unroll
    for (int c = 0; c < 16; c++) {
        int k = lg*8 + c*64;
        float4 s0 = *(float4*)(srow + k);
        float4 s1 = *(float4*)(srow + k + 4);
        s0.x = __expf(s0.x - rmax); s0.y = __expf(s0.y - rmax);
        s0.z = __expf(s0.z - rmax); s0.w = __expf(s0.w - rmax);
        s1.x = __expf(s1.x - rmax); s1.y = __expf(s1.y - rmax);
        s1.z = __expf(s1.z - rmax); s1.w = __expf(s1.w - rmax);
        sum += (s0.x + s0.y + s0.z + s0.w) + (s1.x + s1.y + s1.z + s1.w);
        *(float4*)(srow + k)     = s0;
        *(float4*)(srow + k + 4) = s1;
    }
    red[li*8 + lg] = sum;
    __syncthreads();
    float tsum = 0.f;
#pragma unroll
    for (int m = 0; m < 8; m++) tsum += red[li*8 + m];
    const float inv = 1.f / tsum;

    float* arow = attn_out + (((size_t)(b*NHEAD + n)*SS) + q0 + li) * SS;
#pragma unroll
    for (int c = 0; c < 16; c++) {
        int k = lg*8 + c*64;
        float4 s0 = *(float4*)(srow + k);
        float4 s1 = *(float4*)(srow + k + 4);
        s0.x *= inv; s0.y *= inv; s0.z *= inv; s0.w *= inv;
        s1.x *= inv; s1.y *= inv; s1.z *= inv; s1.w *= inv;
        *(float4*)(arow + k)     = s0;
        *(float4*)(arow + k + 4) = s1;
    }

    // ---- phase 4: context = attn @ V (unnormalized p; 4-way k-split) ----
    float oacc[4][8];
#pragma unroll
    for (int rr = 0; rr < 4; rr++)
#pragma unroll
        for (int cc = 0; cc < 8; cc++) oacc[rr][cc] = 0.f;

    for (int kb = 0; kb < SS; kb += 256) {
        __syncthreads();
#pragma unroll
        for (int p = 0; p < 4; p++) {
            int row = p*64 + lrow;
            const float* src = vh_bn + (size_t)(kb + row)*HDIM + ldo;
            float* dst = tile + row*TSTR + ldo;
#pragma unroll
            for (int c = 0; c < 4; c++)
                *(float4*)(dst + c*4) = *(const float4*)(src + c*4);
        }
        __syncthreads();
#pragma unroll 2
        for (int kk4 = 0; kk4 < 64; kk4 += 4) {
            int kloc = kt*64 + kk4;
            float4 P0 = *(const float4*)(sc + (r0+0)*SCPAD + kb + kloc);
            float4 P1 = *(const float4*)(sc + (r0+1)*SCPAD + kb + kloc);
            float4 P2 = *(const float4*)(sc + (r0+2)*SCPAD + kb + kloc);
            float4 P3 = *(const float4*)(sc + (r0+3)*SCPAD + kb + kloc);
            float pa0[4] = {P0.x, P0.y, P0.z, P0.w};
            float pa1[4] = {P1.x, P1.y, P1.z, P1.w};
            float pa2[4] = {P2.x, P2.y, P2.z, P2.w};
            float pa3[4] = {P3.x, P3.y, P3.z, P3.w};
#pragma unroll
            for (int j = 0; j < 4; j++) {
                const float* vr = tile + (kloc + j)*TSTR + cg*8;
                float4 v0 = *(const float4*)vr;
                float4 v1 = *(const float4*)(vr + 4);
                float vv[8] = {v0.x, v0.y, v0.z, v0.w, v1.x, v1.y, v1.z, v1.w};
#pragma unroll
                for (int cc = 0; cc < 8; cc++) {
                    oacc[0][cc] = fmaf(pa0[j], vv[cc], oacc[0][cc]);
                    oacc[1][cc] = fmaf(pa1[j], vv[cc], oacc[1][cc]);
                    oacc[2][cc] = fmaf(pa2[j], vv[cc], oacc[2][cc]);
                    oacc[3][cc] = fmaf(pa3[j], vv[cc], oacc[3][cc]);
                }
            }
        }
    }
    __syncthreads();
    // reduce 4 k-quarters via smem (reuse tile: 4 * 2048 floats)
    float* part = tile;
#pragma unroll
    for (int rr = 0; rr < 4; rr++) {
        float* dst = part + kt*2048 + (r0+rr)*64 + cg*8;
        *(float4*)dst       = make_float4(oacc[rr][0], oacc[rr][1], oacc[rr][2], oacc[rr][3]);
        *(float4*)(dst + 4) = make_float4(oacc[rr][4], oacc[rr][5], oacc[rr][6], oacc[rr][7]);
    }
    __syncthreads();
    {
        int o = t * 8;   // row = t>>3 == li, d0 = (t&7)*8 == lg*8
        float4 s0 = make_float4(0.f,0.f,0.f,0.f);
        float4 s1 = make_float4(0.f,0.f,0.f,0.f);
#pragma unroll
        for (int kq = 0; kq < 4; kq++) {
            float4 a = *(const float4*)(part + kq*2048 + o);
            float4 c2 = *(const float4*)(part + kq*2048 + o + 4);
            s0.x += a.x;  s0.y += a.y;  s0.z += a.z;  s0.w += a.w;
            s1.x += c2.x; s1.y += c2.y; s1.z += c2.z; s1.w += c2.w;
        }
        float* crow = g_ctx + ((size_t)b*SS + q0 + li) * DMODEL + n*HDIM + lg*8;
        *(float4*)crow       = make_float4(s0.x*inv, s0.y*inv, s0.z*inv, s0.w*inv);
        *(float4*)(crow + 4) = make_float4(s1.x*inv, s1.y*inv, s1.z*inv, s1.w*inv);
    }
}

// ---------------- launcher ----------------
extern "C" void kernel_launch(void* const* d_in, const int* in_sizes, int n_in,
                              void* d_out, int out_size)
{
    (void)in_sizes; (void)n_in; (void)out_size;
    const float* q    = (const float*)d_in[0];
    const float* k    = (const float*)d_in[1];
    const float* v    = (const float*)d_in[2];
    const float* pos  = (const float*)d_in[3];
    const int*   mask = (const int*)d_in[4];
    const float* Wq   = (const float*)d_in[5];
    const float* bq   = (const float*)d_in[6];
    const float* Wk   = (const float*)d_in[7];
    const float* bk   = (const float*)d_in[8];
    const float* Wv   = (const float*)d_in[9];
    const float* bv   = (const float*)d_in[10];
    const float* Wpos = (const float*)d_in[11];
    const float* Wout = (const float*)d_in[12];
    const float* bout = (const float*)d_in[13];
    const float* u    = (const float*)d_in[14];
    const float* vb   = (const float*)d_in[15];

    float *p_qh, *p_kh, *p_vh, *p_ph, *p_ctx;
    cudaGetSymbolAddress((void**)&p_qh,  g_qh);
    cudaGetSymbolAddress((void**)&p_kh,  g_kh);
    cudaGetSymbolAddress((void**)&p_vh,  g_vh);
    cudaGetSymbolAddress((void**)&p_ph,  g_ph);
    cudaGetSymbolAddress((void**)&p_ctx, g_ctx);

    const int smem = (32*SCPAD + 256*TSTR + 32*QSTR + 33*QSTR + 256) * (int)sizeof(float);
    cudaFuncSetAttribute(attn_kernel, cudaFuncAttributeMaxDynamicSharedMemorySize, smem);

    ProjArgs pa;
    pa.X[0] = q;   pa.W[0] = Wq;   pa.bias[0] = bq;      pa.out[0] = p_qh;
    pa.X[1] = k;   pa.W[1] = Wk;   pa.bias[1] = bk;      pa.out[1] = p_kh;
    pa.X[2] = v;   pa.W[2] = Wv;   pa.bias[2] = bv;      pa.out[2] = p_vh;
    pa.X[3] = pos; pa.W[3] = Wpos; pa.bias[3] = nullptr; pa.out[3] = p_ph;
    pa.head_mode = 1;
    pa.count = 4;
    dim3 gproj(DMODEL/128, (BB*SS)/128, 4);
    gemm_kernel<<<gproj, 256>>>(pa);

    float* attn_out = (float*)d_out + (size_t)BB*SS*DMODEL;
    attn_kernel<<<dim3(SS/32, NHEAD, BB), 256, smem>>>(mask, u, vb, attn_out);

    ProjArgs po;
    po.X[0] = p_ctx; po.W[0] = Wout; po.bias[0] = bout; po.out[0] = (float*)d_out;
    po.head_mode = 0;
    po.count = 1;
    dim3 gout(DMODEL/128, (BB*SS)/128, 1);
    gemm_kernel<<<gout, 256>>>(po);
}